// round 13
// baseline (speedup 1.0000x reference)
#include <cuda_runtime.h>
#include <cuda_fp16.h>
#include <cstdint>

#define BATCH 8
#define CH    512
#define HW    1024

// ---------------- scratch ----------------
__device__ __half g_hth [BATCH*HW*CH];            // groupnorm out [b][i][c] fp16
__device__ __half g_qkvh[(size_t)BATCH*HW*1536];  // packed q|k|vT [b][i][0:512|512:1024|1024:1536]
__device__ __half g_vh  [BATCH*CH*HW];            // v [b][c][j]
__device__ float  g_s   [(size_t)BATCH*HW*HW];    // scores fp32 [b][i][j]
__device__ __half g_ah  [(size_t)BATCH*HW*HW];    // attn fp16 [b][i][j]
__device__ __half g_oth [BATCH*HW*CH];            // attn out [b][i][c]
__device__ __half g_wh  [4*CH*CH];                // fp16 weights q,k,v (contig), proj
__device__ float  g_bqkv[1536];                   // packed bias q|k|v
__device__ float  g_mean[64];
__device__ float  g_rstd[64];

// ---------------- helpers ----------------
__device__ __forceinline__ uint32_t smem_u32(const void* p){
    uint32_t a;
    asm("{ .reg .u64 t; cvta.to.shared.u64 t, %1; cvt.u32.u64 %0, t; }" : "=r"(a) : "l"(p));
    return a;
}
__device__ __forceinline__ void cp16(uint32_t dst, const void* src){
    asm volatile("cp.async.cg.shared.global [%0], [%1], 16;" :: "r"(dst), "l"(src) : "memory");
}
__device__ __forceinline__ void cp_commit(){ asm volatile("cp.async.commit_group;" ::: "memory"); }
template<int N> __device__ __forceinline__ void cp_wait(){
    asm volatile("cp.async.wait_group %0;" :: "n"(N) : "memory");
}
__device__ __forceinline__ void ldsm4(uint32_t* r, uint32_t addr){
    asm volatile("ldmatrix.sync.aligned.m8n8.x4.shared.b16 {%0,%1,%2,%3}, [%4];"
        : "=r"(r[0]), "=r"(r[1]), "=r"(r[2]), "=r"(r[3]) : "r"(addr));
}
__device__ __forceinline__ void mma16(float* c, const uint32_t a[4], uint32_t b0, uint32_t b1){
    asm volatile("mma.sync.aligned.m16n8k16.row.col.f32.f16.f16.f32 "
        "{%0,%1,%2,%3}, {%4,%5,%6,%7}, {%8,%9}, {%0,%1,%2,%3};"
        : "+f"(c[0]), "+f"(c[1]), "+f"(c[2]), "+f"(c[3])
        : "r"(a[0]), "r"(a[1]), "r"(a[2]), "r"(a[3]), "r"(b0), "r"(b1));
}
__inline__ __device__ float warp_sum(float v){
    #pragma unroll
    for (int o = 16; o > 0; o >>= 1) v += __shfl_down_sync(0xffffffffu, v, o);
    return v;
}
__inline__ __device__ float warp_allsum(float v){
    #pragma unroll
    for (int o = 16; o > 0; o >>= 1) v += __shfl_xor_sync(0xffffffffu, v, o);
    return v;
}
__inline__ __device__ float warp_allmax(float v){
    #pragma unroll
    for (int o = 16; o > 0; o >>= 1) v = fmaxf(v, __shfl_xor_sync(0xffffffffu, v, o));
    return v;
}

// ================= GroupNorm stats =================
__global__ __launch_bounds__(256) void gn_stats(const float* __restrict__ x){
    int b = blockIdx.x >> 3, g = blockIdx.x & 7;
    const float4* x4 = (const float4*)(x + ((size_t)b*CH + (size_t)g*64)*HW);
    float s = 0.f, ss = 0.f;
    for (int i = threadIdx.x; i < 64*HW/4; i += 256){
        float4 v = x4[i];
        s  += v.x + v.y + v.z + v.w;
        ss += v.x*v.x + v.y*v.y + v.z*v.z + v.w*v.w;
    }
    __shared__ float r1[8], r2[8];
    int w = threadIdx.x >> 5, l = threadIdx.x & 31;
    s = warp_sum(s); ss = warp_sum(ss);
    if (l == 0){ r1[w] = s; r2[w] = ss; }
    __syncthreads();
    if (threadIdx.x == 0){
        float S = 0.f, SS = 0.f;
        #pragma unroll
        for (int i = 0; i < 8; i++){ S += r1[i]; SS += r2[i]; }
        float mean = S * (1.f/(64.f*HW));
        float var  = SS * (1.f/(64.f*HW)) - mean*mean;
        g_mean[blockIdx.x] = mean;
        g_rstd[blockIdx.x] = rsqrtf(var + 1e-5f);
    }
}

// ============ GroupNorm normalize + transpose -> fp16 ============
__global__ __launch_bounds__(256) void gn_t(const float* __restrict__ x,
                                            const float* __restrict__ gamma,
                                            const float* __restrict__ beta){
    __shared__ float t[32][129];
    int b = blockIdx.z, c0 = blockIdx.y*32, i0 = blockIdx.x*128;
    const float* xb = x + ((size_t)b*CH + c0)*HW + i0;
    for (int idx = threadIdx.x; idx < 32*32; idx += 256){
        int r = idx >> 5, f = idx & 31;
        float4 v = *(const float4*)(xb + (size_t)r*HW + f*4);
        t[r][f*4+0] = v.x; t[r][f*4+1] = v.y; t[r][f*4+2] = v.z; t[r][f*4+3] = v.w;
    }
    __syncthreads();
    __half* out = g_hth + ((size_t)b*HW + i0)*CH + c0;
    for (int idx = threadIdx.x; idx < 128*8; idx += 256){
        int i = idx >> 3, cg = idx & 7;
        float o[4];
        #pragma unroll
        for (int e = 0; e < 4; e++){
            int c = cg*4 + e;
            int sidx = b*8 + ((c0 + c) >> 6);
            float sc = gamma[c0+c] * g_rstd[sidx];
            float bi = beta[c0+c] - g_mean[sidx]*sc;
            o[e] = t[c][i]*sc + bi;
        }
        __half2 h0 = __floats2half2_rn(o[0], o[1]);
        __half2 h1 = __floats2half2_rn(o[2], o[3]);
        *(uint2*)(out + (size_t)i*CH + cg*4) =
            make_uint2(*(uint32_t*)&h0, *(uint32_t*)&h1);
    }
}

// ============ weight fp16 convert + bias pack ============
__global__ __launch_bounds__(256) void conv_w(const float* __restrict__ a, const float* __restrict__ b,
                                              const float* __restrict__ c, const float* __restrict__ d,
                                              const float* __restrict__ bq, const float* __restrict__ bk,
                                              const float* __restrict__ bv){
    const float* srcs[4] = {a, b, c, d};
    int z = blockIdx.y;
    const float4* s = (const float4*)srcs[z];
    __half* o = g_wh + (size_t)z*CH*CH;
    int i = blockIdx.x*256 + threadIdx.x;      // 65536 float4
    float4 v = s[i];
    __half2 h0 = __floats2half2_rn(v.x, v.y);
    __half2 h1 = __floats2half2_rn(v.z, v.w);
    *(uint2*)(o + (size_t)i*4) = make_uint2(*(uint32_t*)&h0, *(uint32_t*)&h1);
    if (z == 0 && i < 512) g_bqkv[i] = bq[i];
    if (z == 1 && i < 512) g_bqkv[512 + i] = bk[i];
    if (z == 2 && i < 512) g_bqkv[1024 + i] = bv[i];
}

// ================= mma.sync fp16 GEMM =================
// D[m][n] = scale * sum_k A[m][k]*B[n][k] (+bias_row[m] +bias_col[n] +resid[m][n])
// CTA 128x128, 8 warps (2x4), warp 64x32, K-chunk 64 halves, 3-stage cp.async
// mode: 0 = f32 output, 1 = fp16 output
#define STAGE_BYTES 32768u
#define MM_SMEM (3*STAGE_BYTES)

__global__ __launch_bounds__(256, 2) void mm_tc(
    const __half* __restrict__ A, long long sA, int lda,
    const __half* __restrict__ B, long long sB, int ldb,
    void* __restrict__ Cv, long long sC, int ldc,
    int K,
    const float* __restrict__ bias_row,
    const float* __restrict__ bias_col,
    const float* __restrict__ resid, long long sR,
    float scale, int mode)
{
    extern __shared__ float smem[];
    uint32_t sb = smem_u32(smem);
    int tid = threadIdx.x;
    int wid = tid >> 5, lane = tid & 31;
    int wr = wid >> 2, wc = wid & 3;
    int z = blockIdx.z;
    int m0 = blockIdx.y*128, n0 = blockIdx.x*128;
    const __half* Ab = A + (long long)z*sA + (size_t)m0*lda;
    const __half* Bb = B + (long long)z*sB + (size_t)n0*ldb;

    int frow = tid >> 1;
    int fc0  = (tid & 1) * 4;
    uint32_t fdst = (uint32_t)frow * 128u;
    int fx = frow & 7;

    auto FILL = [&](int st, int kc){
        uint32_t base = sb + (uint32_t)st*STAGE_BYTES;
        const __half* as = Ab + (size_t)frow*lda + kc*64 + fc0*8;
        const __half* bs = Bb + (size_t)frow*ldb + kc*64 + fc0*8;
        #pragma unroll
        for (int j = 0; j < 4; j++){
            uint32_t ph = fdst + (uint32_t)(((fc0 + j) ^ fx) << 4);
            cp16(base + ph, as + j*8);
            cp16(base + 16384u + ph, bs + j*8);
        }
    };

    int lrow = lane & 15, lhalf = lane >> 4;
    uint32_t a_off[4]; int a_x[4];
    #pragma unroll
    for (int mt = 0; mt < 4; mt++){
        int r = wr*64 + mt*16 + lrow;
        a_off[mt] = (uint32_t)r*128u; a_x[mt] = r & 7;
    }
    uint32_t b_off[2]; int b_x[2];
    #pragma unroll
    for (int bt = 0; bt < 2; bt++){
        int r = wc*32 + bt*16 + lrow;
        b_off[bt] = (uint32_t)r*128u; b_x[bt] = r & 7;
    }

    float acc[4][4][4] = {};

    // Interleaved LDSM/MMA: B first, A prefetched one mt-step ahead.
    auto COMPUTE = [&](int st){
        uint32_t ab = sb + (uint32_t)st*STAGE_BYTES;
        uint32_t bb = ab + 16384u;
        #pragma unroll
        for (int ks = 0; ks < 4; ks++){          // 4 x k16 = 64 halves
            uint32_t afr[4][4], bfr[2][4];
            int cidx = ks*2 + lhalf;
            ldsm4(bfr[0], bb + b_off[0] + (uint32_t)((cidx ^ b_x[0]) << 4));
            ldsm4(bfr[1], bb + b_off[1] + (uint32_t)((cidx ^ b_x[1]) << 4));
            ldsm4(afr[0], ab + a_off[0] + (uint32_t)((cidx ^ a_x[0]) << 4));
            #pragma unroll
            for (int mt = 0; mt < 4; mt++){
                if (mt < 3)
                    ldsm4(afr[mt+1], ab + a_off[mt+1] + (uint32_t)((cidx ^ a_x[mt+1]) << 4));
                mma16(acc[mt][0], afr[mt], bfr[0][0], bfr[0][2]);
                mma16(acc[mt][1], afr[mt], bfr[0][1], bfr[0][3]);
                mma16(acc[mt][2], afr[mt], bfr[1][0], bfr[1][2]);
                mma16(acc[mt][3], afr[mt], bfr[1][1], bfr[1][3]);
            }
        }
    };

    int NC = K >> 6;
    FILL(0, 0); cp_commit();
    FILL(1, 1); cp_commit();
    for (int c = 0; c < NC; c++){
        cp_wait<1>();
        __syncthreads();
        if (c + 2 < NC) FILL((c+2)%3, c+2);
        cp_commit();
        COMPUTE(c%3);
    }

    // epilogue
    int g = lane >> 2, t = lane & 3;
    #pragma unroll
    for (int mt = 0; mt < 4; mt++){
        int r1 = m0 + wr*64 + mt*16 + g;
        int r2 = r1 + 8;
        float br1 = bias_row ? __ldg(bias_row + r1) : 0.f;
        float br2 = bias_row ? __ldg(bias_row + r2) : 0.f;
        #pragma unroll
        for (int nt = 0; nt < 4; nt++){
            int col = n0 + wc*32 + nt*8 + t*2;
            float v0 = acc[mt][nt][0]*scale + br1;
            float v1 = acc[mt][nt][1]*scale + br1;
            float v2 = acc[mt][nt][2]*scale + br2;
            float v3 = acc[mt][nt][3]*scale + br2;
            if (bias_col){
                float b0 = __ldg(bias_col + col), b1 = __ldg(bias_col + col + 1);
                v0 += b0; v1 += b1; v2 += b0; v3 += b1;
            }
            if (mode == 0){
                float* C1 = (float*)Cv + (long long)z*sC + (size_t)r1*ldc;
                float* C2 = (float*)Cv + (long long)z*sC + (size_t)r2*ldc;
                if (resid){
                    const float* R1 = resid + (long long)z*sR + (size_t)r1*ldc;
                    const float* R2 = resid + (long long)z*sR + (size_t)r2*ldc;
                    v0 += R1[col]; v1 += R1[col+1]; v2 += R2[col]; v3 += R2[col+1];
                }
                *(float2*)(C1 + col) = make_float2(v0, v1);
                *(float2*)(C2 + col) = make_float2(v2, v3);
            } else {
                __half* C1 = (__half*)Cv + (long long)z*sC + (size_t)r1*ldc;
                __half* C2 = (__half*)Cv + (long long)z*sC + (size_t)r2*ldc;
                *(__half2*)(C1 + col) = __floats2half2_rn(v0, v1);
                *(__half2*)(C2 + col) = __floats2half2_rn(v2, v3);
            }
        }
    }
}

// ============ vT[b][i][c] -> v[b][c][j=i] transpose (fp16, 64x64 tiles) ============
__global__ __launch_bounds__(256) void vt2v(){
    __shared__ __half t[64][72];
    int b = blockIdx.z, c0 = blockIdx.y*64, i0 = blockIdx.x*64;
    int r = threadIdx.x >> 2;           // 0..63
    int cq = (threadIdx.x & 3) * 16;    // 0,16,32,48

    const __half* src = g_qkvh + ((size_t)b*HW + i0 + r)*1536 + 1024 + c0 + cq;
    uint4 a0 = *(const uint4*)src;
    uint4 a1 = *(const uint4*)(src + 8);
    *(uint4*)&t[r][cq]     = a0;
    *(uint4*)&t[r][cq + 8] = a1;
    __syncthreads();

    __align__(16) __half tmp[16];
    #pragma unroll
    for (int e = 0; e < 16; e++) tmp[e] = t[cq + e][r];
    __half* dst = g_vh + ((size_t)b*CH + c0 + r)*HW + i0 + cq;
    *(uint4*)dst       = *(uint4*)tmp;
    *(uint4*)(dst + 8) = *(uint4*)(tmp + 8);
}

// ================= Warp-per-row softmax: f32 scores -> fp16 attn =================
__global__ __launch_bounds__(256) void softmax_kernel(){
    int wid = threadIdx.x >> 5, l = threadIdx.x & 31;
    size_t row = (size_t)blockIdx.x*8 + wid;
    const float4* s4 = (const float4*)(g_s + row*HW);

    float4 v[8];
    #pragma unroll
    for (int j = 0; j < 8; j++) v[j] = s4[j*32 + l];

    float m = -1e30f;
    #pragma unroll
    for (int j = 0; j < 8; j++)
        m = fmaxf(m, fmaxf(fmaxf(v[j].x, v[j].y), fmaxf(v[j].z, v[j].w)));
    m = warp_allmax(m);

    float s = 0.f;
    #pragma unroll
    for (int j = 0; j < 8; j++){
        v[j].x = __expf(v[j].x - m); v[j].y = __expf(v[j].y - m);
        v[j].z = __expf(v[j].z - m); v[j].w = __expf(v[j].w - m);
        s += v[j].x + v[j].y + v[j].z + v[j].w;
    }
    s = warp_allsum(s);
    float inv = 1.f / s;

    uint2* o2 = (uint2*)(g_ah + row*HW);
    #pragma unroll
    for (int j = 0; j < 8; j++){
        __half2 h0 = __floats2half2_rn(v[j].x*inv, v[j].y*inv);
        __half2 h1 = __floats2half2_rn(v[j].z*inv, v[j].w*inv);
        o2[j*32 + l] = make_uint2(*(uint32_t*)&h0, *(uint32_t*)&h1);
    }
}

// ================= launch =================
extern "C" void kernel_launch(void* const* d_in, const int* in_sizes, int n_in,
                              void* d_out, int out_size){
    const float* x  = (const float*)d_in[0];
    const float* gs = (const float*)d_in[1];
    const float* gb = (const float*)d_in[2];
    const float* wq = (const float*)d_in[3];
    const float* bq = (const float*)d_in[4];
    const float* wk = (const float*)d_in[5];
    const float* bk = (const float*)d_in[6];
    const float* wv = (const float*)d_in[7];
    const float* bv = (const float*)d_in[8];
    const float* wp = (const float*)d_in[9];
    const float* bp = (const float*)d_in[10];
    float* out = (float*)d_out;

    cudaFuncSetAttribute(mm_tc, cudaFuncAttributeMaxDynamicSharedMemorySize, MM_SMEM);

    void *p_ht, *p_qkv, *p_v, *p_s, *p_a, *p_ot, *p_w, *p_b;
    cudaGetSymbolAddress(&p_ht,  g_hth);
    cudaGetSymbolAddress(&p_qkv, g_qkvh);
    cudaGetSymbolAddress(&p_v,   g_vh);
    cudaGetSymbolAddress(&p_s,   g_s);
    cudaGetSymbolAddress(&p_a,   g_ah);
    cudaGetSymbolAddress(&p_ot,  g_oth);
    cudaGetSymbolAddress(&p_w,   g_wh);
    cudaGetSymbolAddress(&p_b,   g_bqkv);
    __half* ht  = (__half*)p_ht;  __half* qkv = (__half*)p_qkv;
    __half* vv  = (__half*)p_v;   float* ss = (float*)p_s;   __half* ah = (__half*)p_a;
    __half* ot  = (__half*)p_ot;
    __half* whqkv = (__half*)p_w;                    // rows 0..1535 = wq|wk|wv
    __half* whp   = whqkv + (size_t)3*CH*CH;
    float* bqkv = (float*)p_b;

    const long long NC_  = (long long)HW*CH;
    const long long QKV_ = (long long)HW*1536;
    const long long SS_  = (long long)HW*HW;
    const float scl = 0.044194173824159216f;  // 1/sqrt(512)

    gn_stats<<<64, 256>>>(x);
    conv_w<<<dim3(256, 4), 256>>>(wq, wk, wv, wp, bq, bk, bv);
    gn_t<<<dim3(HW/128, CH/32, BATCH), 256>>>(x, gs, gb);

    // qkv packed: D[i][n] = sum_c Ht[i][c]*Wqkv[n][c] + bqkv[n]  -> fp16, n in [0,1536)
    mm_tc<<<dim3(12, 8, BATCH), 256, MM_SMEM>>>(ht, NC_, CH, whqkv, 0, CH,
        qkv, QKV_, 1536, CH, nullptr, bqkv, nullptr, 0, 1.f, 1);
    // vT[i][c] -> v[c][j]
    vt2v<<<dim3(16, 8, BATCH), 256>>>();
    // scores: S[i][j] = scl * sum_c q[i][c]*k[j][c]  -> f32
    mm_tc<<<dim3(8, 8, BATCH), 256, MM_SMEM>>>(qkv, QKV_, 1536, qkv + 512, QKV_, 1536,
        ss, SS_, HW, CH, nullptr, nullptr, nullptr, 0, scl, 0);
    softmax_kernel<<<BATCH*HW/8, 256>>>();
    // attnout: Ot[i][c] = sum_j attn[i][j]*V[c][j]  -> fp16
    mm_tc<<<dim3(4, 8, BATCH), 256, MM_SMEM>>>(ah, SS_, HW, vv, NC_, HW,
        ot, NC_, CH, HW, nullptr, nullptr, nullptr, 0, 1.f, 1);
    // proj: out[o][i] = sum_c Wp[o][c]*Ot[i][c] + bp[o] + x  -> f32
    mm_tc<<<dim3(8, 4, BATCH), 256, MM_SMEM>>>(whp, 0, CH, ot, NC_, CH,
        out, NC_, HW, CH, bp, nullptr, x, NC_, 1.f, 0);
}

// round 14
// speedup vs baseline: 1.0190x; 1.0190x over previous
#include <cuda_runtime.h>
#include <cuda_fp16.h>
#include <cstdint>

#define BATCH 8
#define CH    512
#define HW    1024

// ---------------- scratch ----------------
__device__ __half g_hth[BATCH*HW*CH];          // groupnorm out [b][i][c] fp16
__device__ __half g_qkh[(size_t)BATCH*HW*1024];// packed q|k [b][i][0:512|512:1024]
__device__ __half g_vh [BATCH*CH*HW];          // v [b][c][j]
__device__ float  g_s  [(size_t)BATCH*HW*HW];  // scores fp32 [b][i][j]
__device__ __half g_ah [(size_t)BATCH*HW*HW];  // attn fp16 [b][i][j]
__device__ __half g_oth[BATCH*HW*CH];          // attn out [b][i][c]
__device__ __half g_wh [4*CH*CH];              // fp16 weights q,k (contig), v, proj
__device__ float  g_bqk[1024];                 // packed bias q|k
__device__ float  g_mean[64];
__device__ float  g_rstd[64];

// ---------------- helpers ----------------
__device__ __forceinline__ uint32_t smem_u32(const void* p){
    uint32_t a;
    asm("{ .reg .u64 t; cvta.to.shared.u64 t, %1; cvt.u32.u64 %0, t; }" : "=r"(a) : "l"(p));
    return a;
}
__device__ __forceinline__ void cp16(uint32_t dst, const void* src){
    asm volatile("cp.async.cg.shared.global [%0], [%1], 16;" :: "r"(dst), "l"(src) : "memory");
}
__device__ __forceinline__ void cp_commit(){ asm volatile("cp.async.commit_group;" ::: "memory"); }
template<int N> __device__ __forceinline__ void cp_wait(){
    asm volatile("cp.async.wait_group %0;" :: "n"(N) : "memory");
}
__device__ __forceinline__ void ldsm4(uint32_t* r, uint32_t addr){
    asm volatile("ldmatrix.sync.aligned.m8n8.x4.shared.b16 {%0,%1,%2,%3}, [%4];"
        : "=r"(r[0]), "=r"(r[1]), "=r"(r[2]), "=r"(r[3]) : "r"(addr));
}
__device__ __forceinline__ void mma16(float* c, const uint32_t a[4], uint32_t b0, uint32_t b1){
    asm volatile("mma.sync.aligned.m16n8k16.row.col.f32.f16.f16.f32 "
        "{%0,%1,%2,%3}, {%4,%5,%6,%7}, {%8,%9}, {%0,%1,%2,%3};"
        : "+f"(c[0]), "+f"(c[1]), "+f"(c[2]), "+f"(c[3])
        : "r"(a[0]), "r"(a[1]), "r"(a[2]), "r"(a[3]), "r"(b0), "r"(b1));
}
__inline__ __device__ float warp_sum(float v){
    #pragma unroll
    for (int o = 16; o > 0; o >>= 1) v += __shfl_down_sync(0xffffffffu, v, o);
    return v;
}
__inline__ __device__ float warp_allsum(float v){
    #pragma unroll
    for (int o = 16; o > 0; o >>= 1) v += __shfl_xor_sync(0xffffffffu, v, o);
    return v;
}
__inline__ __device__ float warp_allmax(float v){
    #pragma unroll
    for (int o = 16; o > 0; o >>= 1) v = fmaxf(v, __shfl_xor_sync(0xffffffffu, v, o));
    return v;
}

// ================= GroupNorm stats =================
__global__ __launch_bounds__(256) void gn_stats(const float* __restrict__ x){
    int b = blockIdx.x >> 3, g = blockIdx.x & 7;
    const float4* x4 = (const float4*)(x + ((size_t)b*CH + (size_t)g*64)*HW);
    float s = 0.f, ss = 0.f;
    for (int i = threadIdx.x; i < 64*HW/4; i += 256){
        float4 v = x4[i];
        s  += v.x + v.y + v.z + v.w;
        ss += v.x*v.x + v.y*v.y + v.z*v.z + v.w*v.w;
    }
    __shared__ float r1[8], r2[8];
    int w = threadIdx.x >> 5, l = threadIdx.x & 31;
    s = warp_sum(s); ss = warp_sum(ss);
    if (l == 0){ r1[w] = s; r2[w] = ss; }
    __syncthreads();
    if (threadIdx.x == 0){
        float S = 0.f, SS = 0.f;
        #pragma unroll
        for (int i = 0; i < 8; i++){ S += r1[i]; SS += r2[i]; }
        float mean = S * (1.f/(64.f*HW));
        float var  = SS * (1.f/(64.f*HW)) - mean*mean;
        g_mean[blockIdx.x] = mean;
        g_rstd[blockIdx.x] = rsqrtf(var + 1e-5f);
    }
}

// ============ GroupNorm normalize + transpose -> fp16 ============
__global__ __launch_bounds__(256) void gn_t(const float* __restrict__ x,
                                            const float* __restrict__ gamma,
                                            const float* __restrict__ beta){
    __shared__ float t[32][129];
    int b = blockIdx.z, c0 = blockIdx.y*32, i0 = blockIdx.x*128;
    const float* xb = x + ((size_t)b*CH + c0)*HW + i0;
    for (int idx = threadIdx.x; idx < 32*32; idx += 256){
        int r = idx >> 5, f = idx & 31;
        float4 v = *(const float4*)(xb + (size_t)r*HW + f*4);
        t[r][f*4+0] = v.x; t[r][f*4+1] = v.y; t[r][f*4+2] = v.z; t[r][f*4+3] = v.w;
    }
    __syncthreads();
    __half* out = g_hth + ((size_t)b*HW + i0)*CH + c0;
    for (int idx = threadIdx.x; idx < 128*8; idx += 256){
        int i = idx >> 3, cg = idx & 7;
        float o[4];
        #pragma unroll
        for (int e = 0; e < 4; e++){
            int c = cg*4 + e;
            int sidx = b*8 + ((c0 + c) >> 6);
            float sc = gamma[c0+c] * g_rstd[sidx];
            float bi = beta[c0+c] - g_mean[sidx]*sc;
            o[e] = t[c][i]*sc + bi;
        }
        __half2 h0 = __floats2half2_rn(o[0], o[1]);
        __half2 h1 = __floats2half2_rn(o[2], o[3]);
        *(uint2*)(out + (size_t)i*CH + cg*4) =
            make_uint2(*(uint32_t*)&h0, *(uint32_t*)&h1);
    }
}

// ============ weight fp16 convert + bias pack ============
__global__ __launch_bounds__(256) void conv_w(const float* __restrict__ a, const float* __restrict__ b,
                                              const float* __restrict__ c, const float* __restrict__ d,
                                              const float* __restrict__ bq, const float* __restrict__ bk){
    const float* srcs[4] = {a, b, c, d};
    int z = blockIdx.y;
    const float4* s = (const float4*)srcs[z];
    __half* o = g_wh + (size_t)z*CH*CH;
    int i = blockIdx.x*256 + threadIdx.x;      // 65536 float4
    float4 v = s[i];
    __half2 h0 = __floats2half2_rn(v.x, v.y);
    __half2 h1 = __floats2half2_rn(v.z, v.w);
    *(uint2*)(o + (size_t)i*4) = make_uint2(*(uint32_t*)&h0, *(uint32_t*)&h1);
    if (z == 0 && i < 512) g_bqk[i] = bq[i];
    if (z == 1 && i < 512) g_bqk[512 + i] = bk[i];
}

// ================= mma.sync fp16 GEMM (R5 tiles + interleaved COMPUTE) =================
// D[m][n] = scale * sum_k A[m][k]*B[n][k] (+bias_row[m] +bias_col[n] +resid[m][n])
// CTA 128x128, 8 warps (2x4), warp 64x32, K-chunk 64 halves, 3-stage cp.async
// mode: 0 = f32 output, 1 = fp16 output
#define STAGE_BYTES 32768u
#define MM_SMEM (3*STAGE_BYTES)

__global__ __launch_bounds__(256, 2) void mm_tc(
    const __half* __restrict__ A, long long sA, int lda,
    const __half* __restrict__ B, long long sB, int ldb,
    void* __restrict__ Cv, long long sC, int ldc,
    int K,
    const float* __restrict__ bias_row,
    const float* __restrict__ bias_col,
    const float* __restrict__ resid, long long sR,
    float scale, int mode)
{
    extern __shared__ float smem[];
    uint32_t sb = smem_u32(smem);
    int tid = threadIdx.x;
    int wid = tid >> 5, lane = tid & 31;
    int wr = wid >> 2, wc = wid & 3;
    int z = blockIdx.z;
    int m0 = blockIdx.y*128, n0 = blockIdx.x*128;
    const __half* Ab = A + (long long)z*sA + (size_t)m0*lda;
    const __half* Bb = B + (long long)z*sB + (size_t)n0*ldb;

    int frow = tid >> 1;
    int fc0  = (tid & 1) * 4;
    uint32_t fdst = (uint32_t)frow * 128u;
    int fx = frow & 7;

    auto FILL = [&](int st, int kc){
        uint32_t base = sb + (uint32_t)st*STAGE_BYTES;
        const __half* as = Ab + (size_t)frow*lda + kc*64 + fc0*8;
        const __half* bs = Bb + (size_t)frow*ldb + kc*64 + fc0*8;
        #pragma unroll
        for (int j = 0; j < 4; j++){
            uint32_t ph = fdst + (uint32_t)(((fc0 + j) ^ fx) << 4);
            cp16(base + ph, as + j*8);
            cp16(base + 16384u + ph, bs + j*8);
        }
    };

    int lrow = lane & 15, lhalf = lane >> 4;
    uint32_t a_off[4]; int a_x[4];
    #pragma unroll
    for (int mt = 0; mt < 4; mt++){
        int r = wr*64 + mt*16 + lrow;
        a_off[mt] = (uint32_t)r*128u; a_x[mt] = r & 7;
    }
    uint32_t b_off[2]; int b_x[2];
    #pragma unroll
    for (int bt = 0; bt < 2; bt++){
        int r = wc*32 + bt*16 + lrow;
        b_off[bt] = (uint32_t)r*128u; b_x[bt] = r & 7;
    }

    float acc[4][4][4] = {};

    // Interleaved LDSM/MMA: B first, A prefetched one mt-step ahead.
    auto COMPUTE = [&](int st){
        uint32_t ab = sb + (uint32_t)st*STAGE_BYTES;
        uint32_t bb = ab + 16384u;
        #pragma unroll
        for (int ks = 0; ks < 4; ks++){          // 4 x k16 = 64 halves
            uint32_t afr[4][4], bfr[2][4];
            int cidx = ks*2 + lhalf;
            ldsm4(bfr[0], bb + b_off[0] + (uint32_t)((cidx ^ b_x[0]) << 4));
            ldsm4(bfr[1], bb + b_off[1] + (uint32_t)((cidx ^ b_x[1]) << 4));
            ldsm4(afr[0], ab + a_off[0] + (uint32_t)((cidx ^ a_x[0]) << 4));
            #pragma unroll
            for (int mt = 0; mt < 4; mt++){
                if (mt < 3)
                    ldsm4(afr[mt+1], ab + a_off[mt+1] + (uint32_t)((cidx ^ a_x[mt+1]) << 4));
                mma16(acc[mt][0], afr[mt], bfr[0][0], bfr[0][2]);
                mma16(acc[mt][1], afr[mt], bfr[0][1], bfr[0][3]);
                mma16(acc[mt][2], afr[mt], bfr[1][0], bfr[1][2]);
                mma16(acc[mt][3], afr[mt], bfr[1][1], bfr[1][3]);
            }
        }
    };

    int NC = K >> 6;
    FILL(0, 0); cp_commit();
    FILL(1, 1); cp_commit();
    for (int c = 0; c < NC; c++){
        cp_wait<1>();
        __syncthreads();
        if (c + 2 < NC) FILL((c+2)%3, c+2);
        cp_commit();
        COMPUTE(c%3);
    }

    // epilogue
    int g = lane >> 2, t = lane & 3;
    #pragma unroll
    for (int mt = 0; mt < 4; mt++){
        int r1 = m0 + wr*64 + mt*16 + g;
        int r2 = r1 + 8;
        float br1 = bias_row ? __ldg(bias_row + r1) : 0.f;
        float br2 = bias_row ? __ldg(bias_row + r2) : 0.f;
        #pragma unroll
        for (int nt = 0; nt < 4; nt++){
            int col = n0 + wc*32 + nt*8 + t*2;
            float v0 = acc[mt][nt][0]*scale + br1;
            float v1 = acc[mt][nt][1]*scale + br1;
            float v2 = acc[mt][nt][2]*scale + br2;
            float v3 = acc[mt][nt][3]*scale + br2;
            if (bias_col){
                float b0 = __ldg(bias_col + col), b1 = __ldg(bias_col + col + 1);
                v0 += b0; v1 += b1; v2 += b0; v3 += b1;
            }
            if (mode == 0){
                float* C1 = (float*)Cv + (long long)z*sC + (size_t)r1*ldc;
                float* C2 = (float*)Cv + (long long)z*sC + (size_t)r2*ldc;
                if (resid){
                    const float* R1 = resid + (long long)z*sR + (size_t)r1*ldc;
                    const float* R2 = resid + (long long)z*sR + (size_t)r2*ldc;
                    v0 += R1[col]; v1 += R1[col+1]; v2 += R2[col]; v3 += R2[col+1];
                }
                *(float2*)(C1 + col) = make_float2(v0, v1);
                *(float2*)(C2 + col) = make_float2(v2, v3);
            } else {
                __half* C1 = (__half*)Cv + (long long)z*sC + (size_t)r1*ldc;
                __half* C2 = (__half*)Cv + (long long)z*sC + (size_t)r2*ldc;
                *(__half2*)(C1 + col) = __floats2half2_rn(v0, v1);
                *(__half2*)(C2 + col) = __floats2half2_rn(v2, v3);
            }
        }
    }
}

// ================= Warp-per-row softmax: f32 scores -> fp16 attn =================
__global__ __launch_bounds__(256) void softmax_kernel(){
    int wid = threadIdx.x >> 5, l = threadIdx.x & 31;
    size_t row = (size_t)blockIdx.x*8 + wid;
    const float4* s4 = (const float4*)(g_s + row*HW);

    float4 v[8];
    #pragma unroll
    for (int j = 0; j < 8; j++) v[j] = s4[j*32 + l];

    float m = -1e30f;
    #pragma unroll
    for (int j = 0; j < 8; j++)
        m = fmaxf(m, fmaxf(fmaxf(v[j].x, v[j].y), fmaxf(v[j].z, v[j].w)));
    m = warp_allmax(m);

    float s = 0.f;
    #pragma unroll
    for (int j = 0; j < 8; j++){
        v[j].x = __expf(v[j].x - m); v[j].y = __expf(v[j].y - m);
        v[j].z = __expf(v[j].z - m); v[j].w = __expf(v[j].w - m);
        s += v[j].x + v[j].y + v[j].z + v[j].w;
    }
    s = warp_allsum(s);
    float inv = 1.f / s;

    uint2* o2 = (uint2*)(g_ah + row*HW);
    #pragma unroll
    for (int j = 0; j < 8; j++){
        __half2 h0 = __floats2half2_rn(v[j].x*inv, v[j].y*inv);
        __half2 h1 = __floats2half2_rn(v[j].z*inv, v[j].w*inv);
        o2[j*32 + l] = make_uint2(*(uint32_t*)&h0, *(uint32_t*)&h1);
    }
}

// ================= launch =================
extern "C" void kernel_launch(void* const* d_in, const int* in_sizes, int n_in,
                              void* d_out, int out_size){
    const float* x  = (const float*)d_in[0];
    const float* gs = (const float*)d_in[1];
    const float* gb = (const float*)d_in[2];
    const float* wq = (const float*)d_in[3];
    const float* bq = (const float*)d_in[4];
    const float* wk = (const float*)d_in[5];
    const float* bk = (const float*)d_in[6];
    const float* wv = (const float*)d_in[7];
    const float* bv = (const float*)d_in[8];
    const float* wp = (const float*)d_in[9];
    const float* bp = (const float*)d_in[10];
    float* out = (float*)d_out;

    cudaFuncSetAttribute(mm_tc, cudaFuncAttributeMaxDynamicSharedMemorySize, MM_SMEM);

    void *p_ht, *p_qk, *p_v, *p_s, *p_a, *p_ot, *p_w, *p_bqk;
    cudaGetSymbolAddress(&p_ht, g_hth);
    cudaGetSymbolAddress(&p_qk, g_qkh);
    cudaGetSymbolAddress(&p_v,  g_vh);
    cudaGetSymbolAddress(&p_s,  g_s);
    cudaGetSymbolAddress(&p_a,  g_ah);
    cudaGetSymbolAddress(&p_ot, g_oth);
    cudaGetSymbolAddress(&p_w,  g_wh);
    cudaGetSymbolAddress(&p_bqk, g_bqk);
    __half* ht = (__half*)p_ht; __half* qk = (__half*)p_qk;
    __half* vv = (__half*)p_v;  float* ss = (float*)p_s;    __half* ah = (__half*)p_a;
    __half* ot = (__half*)p_ot;
    __half* whq = (__half*)p_w;                       // rows 0..511 = wq, 512..1023 = wk
    __half* whv = whq + (size_t)2*CH*CH;
    __half* whp = whv + (size_t)CH*CH;
    float* bqk = (float*)p_bqk;

    const long long NC_ = (long long)HW*CH;
    const long long QK_ = (long long)HW*1024;
    const long long SS_ = (long long)HW*HW;
    const float scl = 0.044194173824159216f;  // 1/sqrt(512)

    gn_stats<<<64, 256>>>(x);
    conv_w<<<dim3(256, 4), 256>>>(wq, wk, wv, wp, bq, bk);
    gn_t<<<dim3(HW/128, CH/32, BATCH), 256>>>(x, gs, gb);

    // qk packed: D[i][n] = sum_c Ht[i][c]*Wqk[n][c] + bqk[n]  -> fp16, n in [0,1024)
    mm_tc<<<dim3(8, 8, BATCH), 256, MM_SMEM>>>(ht, NC_, CH, whq, 0, CH,
        qk, QK_, 1024, CH, nullptr, bqk, nullptr, 0, 1.f, 1);
    // v: D[o][i] = sum_c Wv[o][c]*Ht[i][c] + bv[o]  -> fp16
    mm_tc<<<dim3(8, 4, BATCH), 256, MM_SMEM>>>(whv, 0, CH, ht, NC_, CH,
        vv, NC_, HW, CH, bv, nullptr, nullptr, 0, 1.f, 1);
    // scores: S[i][j] = scl * sum_c q[i][c]*k[j][c]  -> f32
    mm_tc<<<dim3(8, 8, BATCH), 256, MM_SMEM>>>(qk, QK_, 1024, qk + 512, QK_, 1024,
        ss, SS_, HW, CH, nullptr, nullptr, nullptr, 0, scl, 0);
    softmax_kernel<<<BATCH*HW/8, 256>>>();
    // attnout: Ot[i][c] = sum_j attn[i][j]*V[c][j]  -> fp16
    mm_tc<<<dim3(4, 8, BATCH), 256, MM_SMEM>>>(ah, SS_, HW, vv, NC_, HW,
        ot, NC_, CH, HW, nullptr, nullptr, nullptr, 0, 1.f, 1);
    // proj: out[o][i] = sum_c Wp[o][c]*Ot[i][c] + bp[o] + x  -> f32
    mm_tc<<<dim3(8, 4, BATCH), 256, MM_SMEM>>>(whp, 0, CH, ot, NC_, CH,
        out, NC_, HW, CH, bp, nullptr, x, NC_, 1.f, 0);
}

// round 17
// speedup vs baseline: 1.0388x; 1.0194x over previous
#include <cuda_runtime.h>
#include <cuda_fp16.h>
#include <cstdint>

#define BATCH 8
#define CH    512
#define HW    1024

// ---------------- scratch ----------------
__device__ __half g_hth[BATCH*HW*CH];          // groupnorm out [b][i][c] fp16
__device__ __half g_qkh[(size_t)BATCH*HW*1024];// packed q|k [b][i][0:512|512:1024]
__device__ __half g_vh [BATCH*CH*HW];          // v [b][c][j]
__device__ float  g_s  [(size_t)BATCH*HW*HW];  // scores fp32 [b][i][j]
__device__ __half g_ah [(size_t)BATCH*HW*HW];  // attn fp16 [b][i][j]
__device__ __half g_oth[BATCH*HW*CH];          // attn out [b][i][c]
__device__ __half g_wh [4*CH*CH];              // fp16 weights q,k (contig), v, proj
__device__ float  g_bqk[1024];                 // packed bias q|k
__device__ float  g_mean[64];
__device__ float  g_rstd[64];

// ---------------- helpers ----------------
__device__ __forceinline__ uint32_t smem_u32(const void* p){
    uint32_t a;
    asm("{ .reg .u64 t; cvta.to.shared.u64 t, %1; cvt.u32.u64 %0, t; }" : "=r"(a) : "l"(p));
    return a;
}
__device__ __forceinline__ void cp16(uint32_t dst, const void* src){
    asm volatile("cp.async.cg.shared.global [%0], [%1], 16;" :: "r"(dst), "l"(src) : "memory");
}
__device__ __forceinline__ void cp_commit(){ asm volatile("cp.async.commit_group;" ::: "memory"); }
template<int N> __device__ __forceinline__ void cp_wait(){
    asm volatile("cp.async.wait_group %0;" :: "n"(N) : "memory");
}
__device__ __forceinline__ void ldsm4(uint32_t* r, uint32_t addr){
    asm volatile("ldmatrix.sync.aligned.m8n8.x4.shared.b16 {%0,%1,%2,%3}, [%4];"
        : "=r"(r[0]), "=r"(r[1]), "=r"(r[2]), "=r"(r[3]) : "r"(addr));
}
__device__ __forceinline__ void mma16(float* c, const uint32_t a[4], uint32_t b0, uint32_t b1){
    asm volatile("mma.sync.aligned.m16n8k16.row.col.f32.f16.f16.f32 "
        "{%0,%1,%2,%3}, {%4,%5,%6,%7}, {%8,%9}, {%0,%1,%2,%3};"
        : "+f"(c[0]), "+f"(c[1]), "+f"(c[2]), "+f"(c[3])
        : "r"(a[0]), "r"(a[1]), "r"(a[2]), "r"(a[3]), "r"(b0), "r"(b1));
}
__inline__ __device__ float warp_sum(float v){
    #pragma unroll
    for (int o = 16; o > 0; o >>= 1) v += __shfl_down_sync(0xffffffffu, v, o);
    return v;
}
__inline__ __device__ float warp_allsum(float v){
    #pragma unroll
    for (int o = 16; o > 0; o >>= 1) v += __shfl_xor_sync(0xffffffffu, v, o);
    return v;
}
__inline__ __device__ float warp_allmax(float v){
    #pragma unroll
    for (int o = 16; o > 0; o >>= 1) v = fmaxf(v, __shfl_xor_sync(0xffffffffu, v, o));
    return v;
}

// ========== GroupNorm stats (blocks 0..63) + weight convert (blocks 64..1087) ==========
__global__ __launch_bounds__(256) void gn_stats_convw(const float* __restrict__ x,
                                                      const float* __restrict__ wq, const float* __restrict__ wk,
                                                      const float* __restrict__ wv, const float* __restrict__ wp,
                                                      const float* __restrict__ bq, const float* __restrict__ bk){
    if (blockIdx.x < 64){
        int b = blockIdx.x >> 3, g = blockIdx.x & 7;
        const float4* x4 = (const float4*)(x + ((size_t)b*CH + (size_t)g*64)*HW);
        float s = 0.f, ss = 0.f;
        for (int i = threadIdx.x; i < 64*HW/4; i += 256){
            float4 v = x4[i];
            s  += v.x + v.y + v.z + v.w;
            ss += v.x*v.x + v.y*v.y + v.z*v.z + v.w*v.w;
        }
        __shared__ float r1[8], r2[8];
        int w = threadIdx.x >> 5, l = threadIdx.x & 31;
        s = warp_sum(s); ss = warp_sum(ss);
        if (l == 0){ r1[w] = s; r2[w] = ss; }
        __syncthreads();
        if (threadIdx.x == 0){
            float S = 0.f, SS = 0.f;
            #pragma unroll
            for (int i = 0; i < 8; i++){ S += r1[i]; SS += r2[i]; }
            float mean = S * (1.f/(64.f*HW));
            float var  = SS * (1.f/(64.f*HW)) - mean*mean;
            g_mean[blockIdx.x] = mean;
            g_rstd[blockIdx.x] = rsqrtf(var + 1e-5f);
        }
    } else {
        int w = blockIdx.x - 64;              // 0..1023
        int z = w >> 8;                        // 0..3
        int xb = w & 255;
        const float* srcs[4] = {wq, wk, wv, wp};
        const float4* s = (const float4*)srcs[z];
        __half* o = g_wh + (size_t)z*CH*CH;
        int i = xb*256 + threadIdx.x;          // 65536 float4 per z
        float4 v = s[i];
        __half2 h0 = __floats2half2_rn(v.x, v.y);
        __half2 h1 = __floats2half2_rn(v.z, v.w);
        *(uint2*)(o + (size_t)i*4) = make_uint2(*(uint32_t*)&h0, *(uint32_t*)&h1);
        if (z == 0 && i < 512) g_bqk[i] = bq[i];
        if (z == 1 && i < 512) g_bqk[512 + i] = bk[i];
    }
}

// ============ GroupNorm normalize + transpose -> fp16 ============
__global__ __launch_bounds__(256) void gn_t(const float* __restrict__ x,
                                            const float* __restrict__ gamma,
                                            const float* __restrict__ beta){
    __shared__ float t[32][129];
    int b = blockIdx.z, c0 = blockIdx.y*32, i0 = blockIdx.x*128;
    const float* xb = x + ((size_t)b*CH + c0)*HW + i0;
    for (int idx = threadIdx.x; idx < 32*32; idx += 256){
        int r = idx >> 5, f = idx & 31;
        float4 v = *(const float4*)(xb + (size_t)r*HW + f*4);
        t[r][f*4+0] = v.x; t[r][f*4+1] = v.y; t[r][f*4+2] = v.z; t[r][f*4+3] = v.w;
    }
    __syncthreads();
    __half* out = g_hth + ((size_t)b*HW + i0)*CH + c0;
    for (int idx = threadIdx.x; idx < 128*8; idx += 256){
        int i = idx >> 3, cg = idx & 7;
        float o[4];
        #pragma unroll
        for (int e = 0; e < 4; e++){
            int c = cg*4 + e;
            int sidx = b*8 + ((c0 + c) >> 6);
            float sc = gamma[c0+c] * g_rstd[sidx];
            float bi = beta[c0+c] - g_mean[sidx]*sc;
            o[e] = t[c][i]*sc + bi;
        }
        __half2 h0 = __floats2half2_rn(o[0], o[1]);
        __half2 h1 = __floats2half2_rn(o[2], o[3]);
        *(uint2*)(out + (size_t)i*CH + cg*4) =
            make_uint2(*(uint32_t*)&h0, *(uint32_t*)&h1);
    }
}

// ================= mma.sync fp16 GEMM (R5/R12 config) =================
// D[m][n] = scale * sum_k A[m][k]*B[n][k] (+bias_row[m] +bias_col[n] +resid[m][n])
// CTA 128x128, 8 warps (2x4), warp 64x32, K-chunk 64 halves, 3-stage cp.async
// mode: 0 = f32 output, 1 = fp16 output
#define STAGE_BYTES 32768u
#define MM_SMEM (3*STAGE_BYTES)

__global__ __launch_bounds__(256, 2) void mm_tc(
    const __half* __restrict__ A, long long sA, int lda,
    const __half* __restrict__ B, long long sB, int ldb,
    void* __restrict__ Cv, long long sC, int ldc,
    int K,
    const float* __restrict__ bias_row,
    const float* __restrict__ bias_col,
    const float* __restrict__ resid, long long sR,
    float scale, int mode)
{
    extern __shared__ float smem[];
    uint32_t sb = smem_u32(smem);
    int tid = threadIdx.x;
    int wid = tid >> 5, lane = tid & 31;
    int wr = wid >> 2, wc = wid & 3;
    int z = blockIdx.z;
    int m0 = blockIdx.y*128, n0 = blockIdx.x*128;
    const __half* Ab = A + (long long)z*sA + (size_t)m0*lda;
    const __half* Bb = B + (long long)z*sB + (size_t)n0*ldb;

    int frow = tid >> 1;
    int fc0  = (tid & 1) * 4;
    uint32_t fdst = (uint32_t)frow * 128u;
    int fx = frow & 7;

    auto FILL = [&](int st, int kc){
        uint32_t base = sb + (uint32_t)st*STAGE_BYTES;
        const __half* as = Ab + (size_t)frow*lda + kc*64 + fc0*8;
        const __half* bs = Bb + (size_t)frow*ldb + kc*64 + fc0*8;
        #pragma unroll
        for (int j = 0; j < 4; j++){
            uint32_t ph = fdst + (uint32_t)(((fc0 + j) ^ fx) << 4);
            cp16(base + ph, as + j*8);
            cp16(base + 16384u + ph, bs + j*8);
        }
    };

    int lrow = lane & 15, lhalf = lane >> 4;
    uint32_t a_off[4]; int a_x[4];
    #pragma unroll
    for (int mt = 0; mt < 4; mt++){
        int r = wr*64 + mt*16 + lrow;
        a_off[mt] = (uint32_t)r*128u; a_x[mt] = r & 7;
    }
    uint32_t b_off[2]; int b_x[2];
    #pragma unroll
    for (int bt = 0; bt < 2; bt++){
        int r = wc*32 + bt*16 + lrow;
        b_off[bt] = (uint32_t)r*128u; b_x[bt] = r & 7;
    }

    float acc[4][4][4] = {};

    auto COMPUTE = [&](int st){
        uint32_t ab = sb + (uint32_t)st*STAGE_BYTES;
        uint32_t bb = ab + 16384u;
        #pragma unroll
        for (int ks = 0; ks < 4; ks++){          // 4 x k16 = 64 halves
            uint32_t afr[4][4], bfr[2][4];
            int cidx = ks*2 + lhalf;
            #pragma unroll
            for (int mt = 0; mt < 4; mt++)
                ldsm4(afr[mt], ab + a_off[mt] + (uint32_t)((cidx ^ a_x[mt]) << 4));
            #pragma unroll
            for (int bt = 0; bt < 2; bt++)
                ldsm4(bfr[bt], bb + b_off[bt] + (uint32_t)((cidx ^ b_x[bt]) << 4));
            #pragma unroll
            for (int mt = 0; mt < 4; mt++){
                #pragma unroll
                for (int bt = 0; bt < 2; bt++){
                    mma16(acc[mt][bt*2+0], afr[mt], bfr[bt][0], bfr[bt][2]);
                    mma16(acc[mt][bt*2+1], afr[mt], bfr[bt][1], bfr[bt][3]);
                }
            }
        }
    };

    int NC = K >> 6;
    FILL(0, 0); cp_commit();
    FILL(1, 1); cp_commit();
    for (int c = 0; c < NC; c++){
        cp_wait<1>();
        __syncthreads();
        if (c + 2 < NC) FILL((c+2)%3, c+2);
        cp_commit();
        COMPUTE(c%3);
    }

    // epilogue
    int g = lane >> 2, t = lane & 3;
    #pragma unroll
    for (int mt = 0; mt < 4; mt++){
        int r1 = m0 + wr*64 + mt*16 + g;
        int r2 = r1 + 8;
        float br1 = bias_row ? __ldg(bias_row + r1) : 0.f;
        float br2 = bias_row ? __ldg(bias_row + r2) : 0.f;
        #pragma unroll
        for (int nt = 0; nt < 4; nt++){
            int col = n0 + wc*32 + nt*8 + t*2;
            float v0 = acc[mt][nt][0]*scale + br1;
            float v1 = acc[mt][nt][1]*scale + br1;
            float v2 = acc[mt][nt][2]*scale + br2;
            float v3 = acc[mt][nt][3]*scale + br2;
            if (bias_col){
                float b0 = __ldg(bias_col + col), b1 = __ldg(bias_col + col + 1);
                v0 += b0; v1 += b1; v2 += b0; v3 += b1;
            }
            if (mode == 0){
                float* C1 = (float*)Cv + (long long)z*sC + (size_t)r1*ldc;
                float* C2 = (float*)Cv + (long long)z*sC + (size_t)r2*ldc;
                if (resid){
                    const float* R1 = resid + (long long)z*sR + (size_t)r1*ldc;
                    const float* R2 = resid + (long long)z*sR + (size_t)r2*ldc;
                    v0 += R1[col]; v1 += R1[col+1]; v2 += R2[col]; v3 += R2[col+1];
                }
                *(float2*)(C1 + col) = make_float2(v0, v1);
                *(float2*)(C2 + col) = make_float2(v2, v3);
            } else {
                __half* C1 = (__half*)Cv + (long long)z*sC + (size_t)r1*ldc;
                __half* C2 = (__half*)Cv + (long long)z*sC + (size_t)r2*ldc;
                *(__half2*)(C1 + col) = __floats2half2_rn(v0, v1);
                *(__half2*)(C2 + col) = __floats2half2_rn(v2, v3);
            }
        }
    }
}

// ================= Warp-per-row softmax: f32 scores -> fp16 attn =================
__global__ __launch_bounds__(256) void softmax_kernel(){
    int wid = threadIdx.x >> 5, l = threadIdx.x & 31;
    size_t row = (size_t)blockIdx.x*8 + wid;
    const float4* s4 = (const float4*)(g_s + row*HW);

    float4 v[8];
    #pragma unroll
    for (int j = 0; j < 8; j++) v[j] = s4[j*32 + l];

    float m = -1e30f;
    #pragma unroll
    for (int j = 0; j < 8; j++)
        m = fmaxf(m, fmaxf(fmaxf(v[j].x, v[j].y), fmaxf(v[j].z, v[j].w)));
    m = warp_allmax(m);

    float s = 0.f;
    #pragma unroll
    for (int j = 0; j < 8; j++){
        v[j].x = __expf(v[j].x - m); v[j].y = __expf(v[j].y - m);
        v[j].z = __expf(v[j].z - m); v[j].w = __expf(v[j].w - m);
        s += v[j].x + v[j].y + v[j].z + v[j].w;
    }
    s = warp_allsum(s);
    float inv = 1.f / s;

    uint2* o2 = (uint2*)(g_ah + row*HW);
    #pragma unroll
    for (int j = 0; j < 8; j++){
        __half2 h0 = __floats2half2_rn(v[j].x*inv, v[j].y*inv);
        __half2 h1 = __floats2half2_rn(v[j].z*inv, v[j].w*inv);
        o2[j*32 + l] = make_uint2(*(uint32_t*)&h0, *(uint32_t*)&h1);
    }
}

// ================= launch =================
extern "C" void kernel_launch(void* const* d_in, const int* in_sizes, int n_in,
                              void* d_out, int out_size){
    const float* x  = (const float*)d_in[0];
    const float* gs = (const float*)d_in[1];
    const float* gb = (const float*)d_in[2];
    const float* wq = (const float*)d_in[3];
    const float* bq = (const float*)d_in[4];
    const float* wk = (const float*)d_in[5];
    const float* bk = (const float*)d_in[6];
    const float* wv = (const float*)d_in[7];
    const float* bv = (const float*)d_in[8];
    const float* wp = (const float*)d_in[9];
    const float* bp = (const float*)d_in[10];
    float* out = (float*)d_out;

    cudaFuncSetAttribute(mm_tc, cudaFuncAttributeMaxDynamicSharedMemorySize, MM_SMEM);

    void *p_ht, *p_qk, *p_v, *p_s, *p_a, *p_ot, *p_w, *p_bqk;
    cudaGetSymbolAddress(&p_ht, g_hth);
    cudaGetSymbolAddress(&p_qk, g_qkh);
    cudaGetSymbolAddress(&p_v,  g_vh);
    cudaGetSymbolAddress(&p_s,  g_s);
    cudaGetSymbolAddress(&p_a,  g_ah);
    cudaGetSymbolAddress(&p_ot, g_oth);
    cudaGetSymbolAddress(&p_w,  g_wh);
    cudaGetSymbolAddress(&p_bqk, g_bqk);
    __half* ht = (__half*)p_ht; __half* qk = (__half*)p_qk;
    __half* vv = (__half*)p_v;  float* ss = (float*)p_s;    __half* ah = (__half*)p_a;
    __half* ot = (__half*)p_ot;
    __half* whq = (__half*)p_w;                       // rows 0..511 = wq, 512..1023 = wk
    __half* whv = whq + (size_t)2*CH*CH;
    __half* whp = whv + (size_t)CH*CH;
    float* bqk = (float*)p_bqk;

    const long long NC_ = (long long)HW*CH;
    const long long QK_ = (long long)HW*1024;
    const long long SS_ = (long long)HW*HW;
    const float scl = 0.044194173824159216f;  // 1/sqrt(512)

    gn_stats_convw<<<1088, 256>>>(x, wq, wk, wv, wp, bq, bk);
    gn_t<<<dim3(HW/128, CH/32, BATCH), 256>>>(x, gs, gb);

    // qk packed: D[i][n] = sum_c Ht[i][c]*Wqk[n][c] + bqk[n]  -> fp16, n in [0,1024)
    mm_tc<<<dim3(8, 8, BATCH), 256, MM_SMEM>>>(ht, NC_, CH, whq, 0, CH,
        qk, QK_, 1024, CH, nullptr, bqk, nullptr, 0, 1.f, 1);
    // v: D[o][i] = sum_c Wv[o][c]*Ht[i][c] + bv[o]  -> fp16
    mm_tc<<<dim3(8, 4, BATCH), 256, MM_SMEM>>>(whv, 0, CH, ht, NC_, CH,
        vv, NC_, HW, CH, bv, nullptr, nullptr, 0, 1.f, 1);
    // scores: S[i][j] = scl * sum_c q[i][c]*k[j][c]  -> f32
    mm_tc<<<dim3(8, 8, BATCH), 256, MM_SMEM>>>(qk, QK_, 1024, qk + 512, QK_, 1024,
        ss, SS_, HW, CH, nullptr, nullptr, nullptr, 0, scl, 0);
    softmax_kernel<<<BATCH*HW/8, 256>>>();
    // attnout: Ot[i][c] = sum_j attn[i][j]*V[c][j]  -> fp16
    mm_tc<<<dim3(4, 8, BATCH), 256, MM_SMEM>>>(ah, SS_, HW, vv, NC_, HW,
        ot, NC_, CH, HW, nullptr, nullptr, nullptr, 0, 1.f, 1);
    // proj: out[o][i] = sum_c Wp[o][c]*Ot[i][c] + bp[o] + x  -> f32
    mm_tc<<<dim3(8, 4, BATCH), 256, MM_SMEM>>>(whp, 0, CH, ot, NC_, CH,
        out, NC_, HW, CH, bp, nullptr, x, NC_, 1.f, 0);
}